// round 4
// baseline (speedup 1.0000x reference)
#include <cuda_runtime.h>

// BiRealConv2d: y = conv3x3(sign(x), scale_o * sign(w)), pad 1, stride 1.
// Weights here are uniform[0,1)*1e-3 (non-negative) -> sign(w)=+1 a.s., so
// y[n,o,h,w] = scale_o * boxsum3x3(sum_c sign(x))[n,h,w].
// Anomalous weights (sign != +1) are recorded per-channel at deterministic
// slots and patched inline in the output items -> exact for arbitrary data.
//
// Single persistent fused kernel: interleaved work list keeps the channel-sum
// (read stream) ~2 images ahead of the broadcast (write stream) so HBM reads
// and writes overlap. Gating via monotonic epoch counters (graph-replay safe,
// no reset kernel). Grid 592 = 4 blocks/SM x 148 -> all blocks co-resident,
// so spin-waits cannot deadlock.

#define N_    32
#define C_    128
#define H_    112
#define W_    112
#define HW_   (H_ * W_)       // 12544
#define P4_   (HW_ / 4)       // 3136
#define W4_   (W_ / 4)        // 28
#define OC_   128
#define WPO_  (C_ * 9)        // 1152

#define NB_   592             // 4 blocks/SM * 148 SMs (all resident)
#define NWI   64              // weight items (2 output channels each)
#define CSPI  8               // chansum items per image (392 float4 each)
#define OPI   196             // output items per image (256 threads each)
#define LOOK  2               // chansum lookahead (images)
#define GRP   (CSPI + OPI)    // 204
#define NITEMS (NWI + LOOK * CSPI + N_ * GRP)   // 64 + 16 + 6528 = 6608

__device__ __align__(16) float g_T[N_ * HW_];
__device__ float g_scale[OC_];
__device__ int   g_na[OC_];
__device__ signed char g_acode[OC_ * WPO_];      // 0 normal, -1 zero, -2 negative
__device__ unsigned long long g_epoch;           // monotonic across launches
__device__ unsigned long long g_wdone;           // += NWI per launch
__device__ unsigned long long g_csdone[N_];      // += CSPI per launch each

__device__ __forceinline__ float sgnf(float v) {
    return (float)((v > 0.f) - (v < 0.f));
}

__global__ void __launch_bounds__(256, 4)
fused(const float* __restrict__ x, const float* __restrict__ w,
      float* __restrict__ y) {
    const int t = threadIdx.x;
    __shared__ float red[256];
    __shared__ int   cnt[2];
    __shared__ unsigned long long se;

    if (t == 0) se = atomicAdd(&g_epoch, 1ULL) / NB_ + 1ULL;
    __syncthreads();
    const unsigned long long e = se;

    for (int it = blockIdx.x; it < NITEMS; it += NB_) {
        __syncthreads();
        if (it < NWI) {
            // ---- weight item: scales + anomaly codes for 2 output channels
            int half = t >> 7;             // 0/1
            int tl   = t & 127;
            int o    = it * 2 + half;
            if (tl == 0) cnt[half] = 0;
            __syncthreads();
            const float* wo = w + o * WPO_;
            float s = 0.f;
#pragma unroll
            for (int j = 0; j < 9; ++j) {
                int f = tl * 9 + j;
                float v = wo[f];
                s += fabsf(v);
                signed char code = 0;
                if (v <= 0.f) {
                    code = (v < 0.f) ? -2 : -1;   // sign(w)-1
                    atomicAdd(&cnt[half], 1);
                }
                g_acode[o * WPO_ + f] = code;
            }
            red[t] = s;
            __syncthreads();
            for (int off = 64; off > 0; off >>= 1) {
                if (tl < off) red[t] += red[t + off];
                __syncthreads();
            }
            if (tl == 0) {
                g_scale[o] = red[t] / (float)WPO_;
                g_na[o]    = cnt[half];
            }
            __threadfence();
            __syncthreads();
            if (t == 0) atomicAdd(&g_wdone, 1ULL);
            continue;
        }

        int it2 = it - NWI;
        int n, part = -1, op = -1;
        if (it2 < LOOK * CSPI) {                 // prologue chansum
            n = it2 / CSPI; part = it2 % CSPI;
        } else {
            int q = it2 - LOOK * CSPI;
            int g = q / GRP, off = q % GRP;
            if (off < CSPI) {
                n = g + LOOK;
                if (n >= N_) continue;           // no-op slot
                part = off;
            } else {
                n = g; op = off - CSPI;
            }
        }

        if (part >= 0) {
            // ---- chansum item: T[n, f] = sum_c sign(x[n,c,f]) for 392 float4
            int f0 = part * 392 + t;
            bool two = (t < 136);
            int f1 = f0 + 256;
            const float4* xb = reinterpret_cast<const float4*>(x)
                               + (size_t)n * (C_ * P4_);
            float4 a0 = make_float4(0.f, 0.f, 0.f, 0.f);
            float4 a1 = make_float4(0.f, 0.f, 0.f, 0.f);
#pragma unroll 8
            for (int c = 0; c < C_; ++c) {
                const float4* row = xb + (size_t)c * P4_;
                float4 v0 = __ldcs(row + f0);
                a0.x += sgnf(v0.x); a0.y += sgnf(v0.y);
                a0.z += sgnf(v0.z); a0.w += sgnf(v0.w);
                if (two) {
                    float4 v1 = __ldcs(row + f1);
                    a1.x += sgnf(v1.x); a1.y += sgnf(v1.y);
                    a1.z += sgnf(v1.z); a1.w += sgnf(v1.w);
                }
            }
            float4* T4 = reinterpret_cast<float4*>(g_T) + (size_t)n * P4_;
            T4[f0] = a0;
            if (two) T4[f1] = a1;
            __threadfence();
            __syncthreads();
            if (t == 0) atomicAdd(&g_csdone[n], 1ULL);
            continue;
        }

        // ---- output item: y[n, og*8..+8, p4] = scale * boxsum3x3(T)
        if (t == 0) {
            while (atomicAdd(&g_wdone, 0ULL) < 64ULL * e) __nanosleep(128);
            while (atomicAdd(&g_csdone[n], 0ULL) < 8ULL * e) __nanosleep(128);
        }
        __syncthreads();

        int j  = op * 256 + t;       // < 50176
        int og = j / P4_;            // 0..15
        int p4 = j - og * P4_;
        int h  = p4 / W4_;
        int c4 = p4 - h * W4_;

        const float* Tn = g_T + n * HW_;
        float4 acc = make_float4(0.f, 0.f, 0.f, 0.f);
#pragma unroll
        for (int dh = -1; dh <= 1; ++dh) {
            int hh = h + dh;
            if ((unsigned)hh >= (unsigned)H_) continue;
            const float* row = Tn + hh * W_;
            float4 c = reinterpret_cast<const float4*>(row)[c4];
            float  l  = (c4 > 0)       ? row[c4 * 4 - 1] : 0.f;
            float  rr = (c4 < W4_ - 1) ? row[c4 * 4 + 4] : 0.f;
            acc.x += l   + c.x + c.y;
            acc.y += c.x + c.y + c.z;
            acc.z += c.y + c.z + c.w;
            acc.w += c.z + c.w + rr;
        }

        float4* base = reinterpret_cast<float4*>(
            y + ((size_t)(n * OC_ + og * 8)) * HW_) + p4;
#pragma unroll
        for (int jj = 0; jj < 8; ++jj) {
            int o = og * 8 + jj;
            float sc = g_scale[o];
            float4 val = make_float4(sc * acc.x, sc * acc.y,
                                     sc * acc.z, sc * acc.w);
            if (g_na[o] != 0) {
                // exact sparse correction: (sign(w)-1) * sign(x) * scale
                for (int f = 0; f < WPO_; ++f) {
                    int code = (int)g_acode[o * WPO_ + f];
                    if (code == 0) continue;
                    int c  = f / 9, k = f % 9;
                    int dh = k / 3 - 1, dw = k % 3 - 1;
                    int hh = h + dh;
                    if ((unsigned)hh >= (unsigned)H_) continue;
                    const float* xr = x + ((size_t)n * C_ + c) * HW_ + hh * W_;
#pragma unroll
                    for (int q = 0; q < 4; ++q) {
                        int ww = c4 * 4 + q + dw;
                        if ((unsigned)ww >= (unsigned)W_) continue;
                        float add = sc * (float)code * sgnf(xr[ww]);
                        if (q == 0) val.x += add;
                        else if (q == 1) val.y += add;
                        else if (q == 2) val.z += add;
                        else val.w += add;
                    }
                }
            }
            __stcs(base + (size_t)jj * P4_, val);
        }
    }
}

extern "C" void kernel_launch(void* const* d_in, const int* in_sizes, int n_in,
                              void* d_out, int out_size) {
    const float* x = (const float*)d_in[0];
    const float* w = (const float*)d_in[1];
    float* y = (float*)d_out;
    fused<<<NB_, 256>>>(x, w, y);
}

// round 5
// speedup vs baseline: 7.4709x; 7.4709x over previous
#include <cuda_runtime.h>

// BiRealConv2d: y = conv3x3(sign(x), scale_o * sign(w)), pad 1, stride 1.
// Weights here are uniform[0,1)*1e-3 (non-negative) -> sign(w)=+1 a.s., so
// y[n,o,h,w] = scale_o * boxsum3x3(sum_c sign(x))[n,h,w].
// k_weights records any weight with sign != +1 at deterministic slots; the
// fused kernel patches those contributions inline -> exact for any data.
//
// Fused tile kernel: each block owns (image n, 8 output rows). It computes the
// channel-sum T for its rows (+1 halo each side) in smem by reading x, box-sums
// in smem, then broadcast-writes all 128 output channels. No intermediate
// global tensors, no inter-block dependencies; reads and writes overlap.

#define N_    32
#define C_    128
#define H_    112
#define W_    112
#define HW_   (H_ * W_)       // 12544
#define P4_   (HW_ / 4)       // 3136
#define W4_   (W_ / 4)        // 28
#define OC_   128
#define WPO_  (C_ * 9)        // 1152

#define RH    8               // output rows per tile
#define TPI   (H_ / RH)       // 14 tiles per image
#define NTILE (N_ * TPI)      // 448 blocks
#define TT    ((RH + 2) * W4_)  // 280 T float4 tasks
#define ST    (RH * W4_)        // 224 S float4 tasks

__device__ float g_scale[OC_];
__device__ int   g_na[OC_];
__device__ signed char g_acode[OC_ * WPO_];   // 0 normal, -1 zero, -2 negative

__device__ __forceinline__ float sgnf(float v) {
    return (float)((v > 0.f) - (v < 0.f));
}

// Per-output-channel scale (mean |w|) + anomaly codes (sign(w) != +1).
__global__ void k_weights(const float* __restrict__ w) {
    int o = blockIdx.x;          // 0..127
    int t = threadIdx.x;         // 0..127, 9 consecutive weights each
    const float* wo = w + o * WPO_;
    float s = 0.f;
    int   na = 0;
#pragma unroll
    for (int j = 0; j < 9; ++j) {
        int f = t * 9 + j;
        float v = wo[f];
        s += fabsf(v);
        signed char code = 0;
        if (v <= 0.f) { code = (v < 0.f) ? -2 : -1; na = 1; }
        g_acode[o * WPO_ + f] = code;
    }
    __shared__ float red[128];
    __shared__ int   redi[128];
    red[t] = s; redi[t] = na;
    __syncthreads();
    for (int off = 64; off > 0; off >>= 1) {
        if (t < off) { red[t] += red[t + off]; redi[t] |= redi[t + off]; }
        __syncthreads();
    }
    if (t == 0) { g_scale[o] = red[0] / (float)WPO_; g_na[o] = redi[0]; }
}

__global__ void __launch_bounds__(256, 4)
fused(const float* __restrict__ x, float* __restrict__ y) {
    const int t    = threadIdx.x;
    const int tile = blockIdx.x;
    const int n    = tile / TPI;
    const int h0   = (tile - n * TPI) * RH;

    __shared__ float Ts[(RH + 2) * W_];   // channel-sum rows h0-1 .. h0+RH
    __shared__ float Ss[RH * W_];         // box-summed rows h0 .. h0+RH-1
    __shared__ float s_scale[OC_];
    __shared__ int   s_na[OC_];

    if (t < OC_) { s_scale[t] = g_scale[t]; s_na[t] = g_na[t]; }

    // Phase 1: T rows (with halo). Out-of-range rows -> 0 (zero padding).
    const float4* xb = reinterpret_cast<const float4*>(x) + (size_t)n * (C_ * P4_);
    for (int task = t; task < TT; task += 256) {
        int row = task / W4_;             // 0..RH+1
        int c4  = task - row * W4_;
        int gh  = h0 - 1 + row;
        float4 acc = make_float4(0.f, 0.f, 0.f, 0.f);
        if ((unsigned)gh < (unsigned)H_) {
            const float4* p = xb + gh * W4_ + c4;
#pragma unroll 8
            for (int c = 0; c < C_; ++c) {
                float4 v = p[(size_t)c * P4_];
                acc.x += sgnf(v.x); acc.y += sgnf(v.y);
                acc.z += sgnf(v.z); acc.w += sgnf(v.w);
            }
        }
        reinterpret_cast<float4*>(Ts)[task] = acc;
    }
    __syncthreads();

    // Phase 2: 3x3 box sum (horizontal zero padding at tile-column edges).
    for (int task = t; task < ST; task += 256) {
        int r  = task / W4_;
        int c4 = task - r * W4_;
        float4 acc = make_float4(0.f, 0.f, 0.f, 0.f);
#pragma unroll
        for (int rr = r; rr < r + 3; ++rr) {
            const float* row = Ts + rr * W_;
            float4 c = reinterpret_cast<const float4*>(row)[c4];
            float  l  = (c4 > 0)        ? row[c4 * 4 - 1] : 0.f;
            float  rg = (c4 < W4_ - 1)  ? row[c4 * 4 + 4] : 0.f;
            acc.x += l   + c.x + c.y;
            acc.y += c.x + c.y + c.z;
            acc.z += c.y + c.z + c.w;
            acc.w += c.z + c.w + rg;
        }
        reinterpret_cast<float4*>(Ss)[task] = acc;
    }
    __syncthreads();

    // Phase 3: broadcast-write 128 channels. j = o*ST + pos, 112 per thread.
    float* yn = y + (size_t)n * OC_ * HW_;
#pragma unroll 4
    for (int k = 0; k < (OC_ * ST) / 256; ++k) {
        int j   = t + 256 * k;
        int o   = j / ST;
        int pos = j - o * ST;
        int r   = pos / W4_;
        int c4  = pos - r * W4_;
        float sc = s_scale[o];
        float4 s = reinterpret_cast<const float4*>(Ss)[pos];
        float4 val = make_float4(sc * s.x, sc * s.y, sc * s.z, sc * s.w);
        if (s_na[o] != 0) {
            // exact sparse correction: scale * (sign(w)-1) * sign(x)
            int h = h0 + r;
            for (int f = 0; f < WPO_; ++f) {
                int code = (int)g_acode[o * WPO_ + f];
                if (code == 0) continue;
                int c  = f / 9, kk = f % 9;
                int dh = kk / 3 - 1, dw = kk % 3 - 1;
                int hh = h + dh;
                if ((unsigned)hh >= (unsigned)H_) continue;
                const float* xr = x + ((size_t)n * C_ + c) * HW_ + hh * W_;
#pragma unroll
                for (int q = 0; q < 4; ++q) {
                    int ww = c4 * 4 + q + dw;
                    if ((unsigned)ww >= (unsigned)W_) continue;
                    float add = sc * (float)code * sgnf(xr[ww]);
                    if (q == 0) val.x += add;
                    else if (q == 1) val.y += add;
                    else if (q == 2) val.z += add;
                    else val.w += add;
                }
            }
        }
        __stcs(reinterpret_cast<float4*>(yn + (size_t)o * HW_ + (h0 + r) * W_) + c4,
               val);
    }
}

extern "C" void kernel_launch(void* const* d_in, const int* in_sizes, int n_in,
                              void* d_out, int out_size) {
    const float* x = (const float*)d_in[0];
    const float* w = (const float*)d_in[1];
    float* y = (float*)d_out;
    k_weights<<<OC_, 128>>>(w);
    fused<<<NTILE, 256>>>(x, y);
}

// round 8
// speedup vs baseline: 7.6612x; 1.0255x over previous
#include <cuda_runtime.h>

// BiRealConv2d: y = conv3x3(sign(x), scale_o * sign(w)), pad 1, stride 1.
// Weights here are uniform[0,1)*1e-3 (non-negative) -> sign(w)=+1 a.s., so
// y[n,o,h,w] = scale_o * boxsum3x3(sum_c sign(x))[n,h,w].
// Blocks 0..127 record any weight with sign != +1 at deterministic slots;
// phase 3 patches those contributions inline -> exact for arbitrary data.
//
// ONE kernel. Each block owns (image, 8 output rows): channel-sum T (+halo)
// into smem, per-thread 3x3 box-sum into registers, broadcast-store all 128
// output channels. Weight scales are produced by blocks 0..127 up front and
// consumed at phase 3 behind a monotonic counter (epoch-derived bound ->
// graph-replay safe; producers never wait and all blocks are co-resident,
// so the wait cannot deadlock and is ~zero in practice).

#define N_    32
#define C_    128
#define H_    112
#define W_    112
#define HW_   (H_ * W_)       // 12544
#define P4_   (HW_ / 4)       // 3136
#define W4_   (W_ / 4)        // 28
#define OC_   128
#define WPO_  (C_ * 9)        // 1152
#define WPO4_ (WPO_ / 4)      // 288

#define RH    8               // output rows per tile
#define TPI   (H_ / RH)       // 14 tiles per image
#define NTILE (N_ * TPI)      // 448 blocks
#define TT    ((RH + 2) * W4_)  // 280 T float4 tasks
#define ST    (RH * W4_)        // 224 box-sum positions

__device__ float g_scale[OC_];
__device__ int   g_na[OC_];
__device__ signed char g_acode[OC_ * WPO_];   // 0 normal, -1 zero, -2 negative
__device__ unsigned long long g_epoch;        // monotonic across launches
__device__ unsigned long long g_wdone;        // +=OC_ per launch

__device__ __forceinline__ float sgnf(float v) {
    return (float)((v > 0.f) - (v < 0.f));
}

__global__ void __launch_bounds__(256, 4)
fused(const float* __restrict__ x, const float* __restrict__ w,
      float* __restrict__ y) {
    const int t    = threadIdx.x;
    const int tile = blockIdx.x;
    const int n    = tile / TPI;
    const int h0   = (tile - n * TPI) * RH;

    __shared__ float Ts[(RH + 2) * W_];   // channel-sum rows h0-1 .. h0+RH
    __shared__ float s_scale[OC_];
    __shared__ int   s_na[OC_];
    __shared__ float red[256];
    __shared__ unsigned long long se;

    if (t == 0) se = atomicAdd(&g_epoch, 1ULL) / NTILE + 1ULL;
    __syncthreads();
    const unsigned long long e = se;

    // ---- producer duty: blocks 0..127 emit scale/anomaly data for channel o
    if (tile < OC_) {
        const int o = tile;
        const float4* wo = reinterpret_cast<const float4*>(w + o * WPO_);
        float s = 0.f;
        int   na = 0;
        for (int j = t; j < WPO4_; j += 256) {
            float4 v = wo[j];
            const float vv[4] = {v.x, v.y, v.z, v.w};
#pragma unroll
            for (int q = 0; q < 4; ++q) {
                s += fabsf(vv[q]);
                signed char code = 0;
                if (vv[q] <= 0.f) { code = (vv[q] < 0.f) ? -2 : -1; na = 1; }
                g_acode[o * WPO_ + j * 4 + q] = code;
            }
        }
        red[t] = s;
        int any = __syncthreads_or(na);
        for (int off = 128; off > 0; off >>= 1) {
            if (t < off) red[t] += red[t + off];
            __syncthreads();
        }
        if (t == 0) {
            g_scale[o] = red[0] / (float)WPO_;
            g_na[o]    = any;
            __threadfence();
            atomicAdd(&g_wdone, 1ULL);
        }
        __syncthreads();
    }

    // ---- phase 1: channel-sum rows h0-1 .. h0+RH into smem
    const float4* xb = reinterpret_cast<const float4*>(x) + (size_t)n * (C_ * P4_);
    for (int task = t; task < TT; task += 256) {
        int row = task / W4_;             // 0..RH+1
        int c4  = task - row * W4_;
        int gh  = h0 - 1 + row;
        float4 acc = make_float4(0.f, 0.f, 0.f, 0.f);
        if ((unsigned)gh < (unsigned)H_) {
            const float4* p = xb + gh * W4_ + c4;
#pragma unroll 8
            for (int c = 0; c < C_; ++c) {
                float4 v = p[(size_t)c * P4_];
                acc.x += sgnf(v.x); acc.y += sgnf(v.y);
                acc.z += sgnf(v.z); acc.w += sgnf(v.w);
            }
        }
        reinterpret_cast<float4*>(Ts)[task] = acc;
    }
    __syncthreads();

    // ---- weights ready? (zero wait in practice: weights finish in ~2us,
    //      phase 1 takes ~35us). Then stage scales in smem.
    if (t == 0) {
        while (atomicAdd(&g_wdone, 0ULL) < (unsigned long long)OC_ * e)
            __nanosleep(64);
    }
    __syncthreads();
    if (t < OC_) { s_scale[t] = g_scale[t]; s_na[t] = g_na[t]; }
    __syncthreads();

    // ---- phase 2+3: per-thread box-sum (registers), then broadcast-store
    if (t < ST) {
        const int r  = t / W4_;
        const int c4 = t - r * W4_;
        float4 acc = make_float4(0.f, 0.f, 0.f, 0.f);
#pragma unroll
        for (int rr = r; rr < r + 3; ++rr) {
            const float* row = Ts + rr * W_;
            float4 c = reinterpret_cast<const float4*>(row)[c4];
            float  l  = (c4 > 0)        ? row[c4 * 4 - 1] : 0.f;
            float  rg = (c4 < W4_ - 1)  ? row[c4 * 4 + 4] : 0.f;
            acc.x += l   + c.x + c.y;
            acc.y += c.x + c.y + c.z;
            acc.z += c.y + c.z + c.w;
            acc.w += c.z + c.w + rg;
        }

        float4* y4 = reinterpret_cast<float4*>(y)
                   + (size_t)n * (OC_ * P4_) + (h0 + r) * W4_ + c4;
#pragma unroll 4
        for (int o = 0; o < OC_; ++o) {
            float sc = s_scale[o];
            float4 val = make_float4(sc * acc.x, sc * acc.y,
                                     sc * acc.z, sc * acc.w);
            if (s_na[o] != 0) {
                // exact sparse correction: scale * (sign(w)-1) * sign(x)
                const int h = h0 + r;
                for (int f = 0; f < WPO_; ++f) {
                    int code = (int)g_acode[o * WPO_ + f];
                    if (code == 0) continue;
                    int c  = f / 9, kk = f % 9;
                    int dh = kk / 3 - 1, dw = kk % 3 - 1;
                    int hh = h + dh;
                    if ((unsigned)hh >= (unsigned)H_) continue;
                    const float* xr = x + ((size_t)n * C_ + c) * HW_ + hh * W_;
#pragma unroll
                    for (int q = 0; q < 4; ++q) {
                        int ww = c4 * 4 + q + dw;
                        if ((unsigned)ww >= (unsigned)W_) continue;
                        float add = sc * (float)code * sgnf(xr[ww]);
                        if (q == 0) val.x += add;
                        else if (q == 1) val.y += add;
                        else if (q == 2) val.z += add;
                        else val.w += add;
                    }
                }
            }
            __stcs(y4 + (size_t)o * P4_, val);
        }
    }
}

extern "C" void kernel_launch(void* const* d_in, const int* in_sizes, int n_in,
                              void* d_out, int out_size) {
    const float* x = (const float*)d_in[0];
    const float* w = (const float*)d_in[1];
    float* y = (float*)d_out;
    fused<<<NTILE, 256>>>(x, w, y);
}

// round 11
// speedup vs baseline: 8.5306x; 1.1135x over previous
#include <cuda_runtime.h>

// BiRealConv2d: y = conv3x3(sign(x), scale_o * sign(w)), pad 1, stride 1.
// Weights here are uniform[0,1)*1e-3 (non-negative) -> sign(w)=+1 a.s., so
// y[n,o,h,w] = scale_o * boxsum3x3(sum_c sign(x))[n,h,w].
// Blocks 0..127 record any weight with sign != +1 at deterministic slots;
// phase 3 patches those contributions inline -> exact for arbitrary data.
//
// ONE kernel, 288 threads/block. Each block owns (image, 8 output rows):
// channel-sum T (+halo) into smem -- 280 tasks over 288 threads = ONE
// balanced round (the previous 256-thread version ran a crippled second
// round on 24 threads) -- then per-thread 3x3 box-sum in registers and
// broadcast-store of all 128 output channels. Weight scales are produced by
// blocks 0..127 before their tile work and consumed at phase 3 behind a
// monotonic counter (graph-replay safe; producers never wait and all blocks
// are co-resident, so the wait cannot deadlock; it is ~zero in practice).

#define N_    32
#define C_    128
#define H_    112
#define W_    112
#define HW_   (H_ * W_)       // 12544
#define P4_   (HW_ / 4)       // 3136
#define W4_   (W_ / 4)        // 28
#define OC_   128
#define WPO_  (C_ * 9)        // 1152
#define WPO4_ (WPO_ / 4)      // 288

#define TPB   288             // 9 warps
#define RH    8               // output rows per tile
#define TPI   (H_ / RH)       // 14 tiles per image
#define NTILE (N_ * TPI)      // 448 blocks
#define TT    ((RH + 2) * W4_)  // 280 T float4 tasks  (<= TPB, one round)
#define ST    (RH * W4_)        // 224 box-sum positions

__device__ float g_scale[OC_];
__device__ int   g_na[OC_];
__device__ signed char g_acode[OC_ * WPO_];   // 0 normal, -1 zero, -2 negative
__device__ unsigned long long g_epoch;        // monotonic across launches
__device__ unsigned long long g_wdone;        // +=OC_ per launch

__device__ __forceinline__ float sgnf(float v) {
    return (float)((v > 0.f) - (v < 0.f));
}

__global__ void __launch_bounds__(TPB, 4)
fused(const float* __restrict__ x, const float* __restrict__ w,
      float* __restrict__ y) {
    const int t    = threadIdx.x;
    const int tile = blockIdx.x;
    const int n    = tile / TPI;
    const int h0   = (tile - n * TPI) * RH;

    __shared__ float Ts[(RH + 2) * W_];   // channel-sum rows h0-1 .. h0+RH
    __shared__ float s_scale[OC_];
    __shared__ int   s_na[OC_];
    __shared__ float red[TPB];
    __shared__ unsigned long long se;

    if (t == 0) se = atomicAdd(&g_epoch, 1ULL) / NTILE + 1ULL;
    __syncthreads();
    const unsigned long long e = se;

    // ---- producer duty: blocks 0..127 emit scale/anomaly data for channel o
    if (tile < OC_) {
        const int o = tile;
        // exactly one float4 per thread (WPO4_ == TPB)
        float4 v = reinterpret_cast<const float4*>(w + o * WPO_)[t];
        const float vv[4] = {v.x, v.y, v.z, v.w};
        float s = 0.f;
        int   na = 0;
#pragma unroll
        for (int q = 0; q < 4; ++q) {
            s += fabsf(vv[q]);
            signed char code = 0;
            if (vv[q] <= 0.f) { code = (vv[q] < 0.f) ? -2 : -1; na = 1; }
            g_acode[o * WPO_ + t * 4 + q] = code;
        }
        red[t] = s;
        int any = __syncthreads_or(na);
        // deterministic tree reduce over 288 = 2*144
        if (t < 144) red[t] += red[t + 144];
        __syncthreads();
        if (t < 72)  red[t] += red[t + 72];
        __syncthreads();
        if (t < 36)  red[t] += red[t + 36];
        __syncthreads();
        if (t < 18)  red[t] += red[t + 18];
        __syncthreads();
        if (t < 9)   red[t] += red[t + 9];
        __syncthreads();
        if (t == 0) {
            float tot = 0.f;
#pragma unroll
            for (int q = 0; q < 9; ++q) tot += red[q];
            g_scale[o] = tot / (float)WPO_;
            g_na[o]    = any;
            __threadfence();
            atomicAdd(&g_wdone, 1ULL);
        }
        __syncthreads();
    }

    // ---- phase 1: channel-sum rows h0-1 .. h0+RH into smem (one round)
    if (t < TT) {
        int row = t / W4_;                // 0..RH+1
        int c4  = t - row * W4_;
        int gh  = h0 - 1 + row;
        float4 acc = make_float4(0.f, 0.f, 0.f, 0.f);
        if ((unsigned)gh < (unsigned)H_) {
            const float4* p = reinterpret_cast<const float4*>(x)
                            + (size_t)n * (C_ * P4_) + gh * W4_ + c4;
#pragma unroll 8
            for (int c = 0; c < C_; ++c) {
                float4 v = p[(size_t)c * P4_];
                acc.x += sgnf(v.x); acc.y += sgnf(v.y);
                acc.z += sgnf(v.z); acc.w += sgnf(v.w);
            }
        }
        reinterpret_cast<float4*>(Ts)[t] = acc;
    }
    __syncthreads();

    // ---- weights ready? (zero wait in practice). Stage scales in smem.
    if (t == 0) {
        while (atomicAdd(&g_wdone, 0ULL) < (unsigned long long)OC_ * e)
            __nanosleep(64);
    }
    __syncthreads();
    if (t < OC_) { s_scale[t] = g_scale[t]; s_na[t] = g_na[t]; }
    __syncthreads();

    // ---- phase 2+3: per-thread box-sum (registers), then broadcast-store
    if (t < ST) {
        const int r  = t / W4_;
        const int c4 = t - r * W4_;
        float4 acc = make_float4(0.f, 0.f, 0.f, 0.f);
#pragma unroll
        for (int rr = r; rr < r + 3; ++rr) {
            const float* row = Ts + rr * W_;
            float4 c = reinterpret_cast<const float4*>(row)[c4];
            float  l  = (c4 > 0)        ? row[c4 * 4 - 1] : 0.f;
            float  rg = (c4 < W4_ - 1)  ? row[c4 * 4 + 4] : 0.f;
            acc.x += l   + c.x + c.y;
            acc.y += c.x + c.y + c.z;
            acc.z += c.y + c.z + c.w;
            acc.w += c.z + c.w + rg;
        }

        float4* y4 = reinterpret_cast<float4*>(y)
                   + (size_t)n * (OC_ * P4_) + (h0 + r) * W4_ + c4;
#pragma unroll 4
        for (int o = 0; o < OC_; ++o) {
            float sc = s_scale[o];
            float4 val = make_float4(sc * acc.x, sc * acc.y,
                                     sc * acc.z, sc * acc.w);
            if (s_na[o] != 0) {
                // exact sparse correction: scale * (sign(w)-1) * sign(x)
                const int h = h0 + r;
                for (int f = 0; f < WPO_; ++f) {
                    int code = (int)g_acode[o * WPO_ + f];
                    if (code == 0) continue;
                    int c  = f / 9, kk = f % 9;
                    int dh = kk / 3 - 1, dw = kk % 3 - 1;
                    int hh = h + dh;
                    if ((unsigned)hh >= (unsigned)H_) continue;
                    const float* xr = x + ((size_t)n * C_ + c) * HW_ + hh * W_;
#pragma unroll
                    for (int q = 0; q < 4; ++q) {
                        int ww = c4 * 4 + q + dw;
                        if ((unsigned)ww >= (unsigned)W_) continue;
                        float add = sc * (float)code * sgnf(xr[ww]);
                        if (q == 0) val.x += add;
                        else if (q == 1) val.y += add;
                        else if (q == 2) val.z += add;
                        else val.w += add;
                    }
                }
            }
            __stcs(y4 + (size_t)o * P4_, val);
        }
    }
}

extern "C" void kernel_launch(void* const* d_in, const int* in_sizes, int n_in,
                              void* d_out, int out_size) {
    const float* x = (const float*)d_in[0];
    const float* w = (const float*)d_in[1];
    float* y = (float*)d_out;
    fused<<<NTILE, TPB>>>(x, w, y);
}